// round 13
// baseline (speedup 1.0000x reference)
#include <cuda_runtime.h>

// B=32, S=12, F=128, K=8, H=64, C=64, N=512
#define BB    32
#define SEQ   12
#define FF    128
#define KK    8
#define HH    64
#define CC    64
#define NNN   512
#define NBLK  256                    // (b,k) stage1 blocks; blocks 0..63 also own Wf col
#define NOWN  64                     // Wf owner blocks (one output column each)
#define TPB   256

// Scratch + sync (allocation-free rule: __device__ globals)
__device__ float g_hcat[BB * KK * HH];    // 32 x 512 elu(Wh_row)
__device__ unsigned int g_tick = 0;       // epoch tickets (monotonic across replays)
__device__ unsigned int g_d1 = 0;         // stage-1 done count

__device__ __forceinline__ void spin_until(volatile unsigned int* p, unsigned int target)
{
    while (*p < target) { __nanosleep(32); }
}

__global__ void __launch_bounds__(TPB, 2) gat_fused(
    const float* __restrict__ x,        // (32,12,128)
    const float* __restrict__ W_heads,  // (8,128,64)
    const float* __restrict__ W_out,    // (512,64)
    const float* __restrict__ Wf,       // (64, 512*64)
    const float* __restrict__ bf,       // (64,)
    float* __restrict__ out)            // (32,64)
{
    __shared__ float smem[1664];          // region-reused (syncs separate uses)
    __shared__ unsigned int s_epoch;      // t==0 only
    const int blk = blockIdx.x;
    const int t   = threadIdx.x;

    if (t == 0) s_epoch = atomicAdd(&g_tick, 1u) / NBLK;

    // ---------- stage-1 task (all blocks): (b,k) ----------
    const int b = blk >> 3, k = blk & 7;

    float* s_x = smem;                    // 128 (aliased by s4 later; sync separates)
    if (t < FF) s_x[t] = x[b * SEQ * FF + (SEQ - 1) * FF + t];

    // ---------- Wf owner setup: first 8-load batch starts the DRAM stream ----------
    const bool owner = (blk < NOWN);
    const int cp = blk;                   // valid when owner
    const float4* src4 = (const float4*)(Wf + (size_t)cp * (NNN * CC));
    const int c4 = t & 15;                // float4 column
    const int nl = t >> 4;                // 0..15
    float4 v0, v1, v2, v3, v4, v5, v6, v7;
    if (owner) {
        v0 = src4[(nl      ) * 16 + c4];
        v1 = src4[(nl +  16) * 16 + c4];
        v2 = src4[(nl +  32) * 16 + c4];
        v3 = src4[(nl +  48) * 16 + c4];
        v4 = src4[(nl +  64) * 16 + c4];
        v5 = src4[(nl +  80) * 16 + c4];
        v6 = src4[(nl +  96) * 16 + c4];
        v7 = src4[(nl + 112) * 16 + c4];
    }

    __syncthreads();                      // s_x ready

    // ---------- stage1 (R8-measured-best variant): 4 threads per h ----------
    {
        const int h  = t >> 2;
        const int fg = t & 3;
        const float* wp = W_heads + (size_t)k * FF * HH + h;
        float acc = 0.f;
        #pragma unroll
        for (int i = 0; i < 32; ++i) {
            const int f = fg * 32 + i;
            acc = fmaf(s_x[f], wp[f * HH], acc);
        }
        acc += __shfl_down_sync(0xffffffffu, acc, 2);
        acc += __shfl_down_sync(0xffffffffu, acc, 1);
        if (fg == 0)
            g_hcat[b * (KK * HH) + k * HH + h] = acc > 0.f ? acc : expm1f(acc);
    }
    __threadfence();
    __syncthreads();
    if (t == 0) atomicAdd(&g_d1, 1u);

    if (!owner) return;                   // non-owner blocks done

    // ---------- remaining 24 Wf loads (3 batches), accumulate ----------
    float4 a;
    a.x = ((v0.x + v1.x) + (v2.x + v3.x)) + ((v4.x + v5.x) + (v6.x + v7.x));
    a.y = ((v0.y + v1.y) + (v2.y + v3.y)) + ((v4.y + v5.y) + (v6.y + v7.y));
    a.z = ((v0.z + v1.z) + (v2.z + v3.z)) + ((v4.z + v5.z) + (v6.z + v7.z));
    a.w = ((v0.w + v1.w) + (v2.w + v3.w)) + ((v4.w + v5.w) + (v6.w + v7.w));
    #pragma unroll
    for (int g = 1; g < 4; ++g) {
        float4 u0 = src4[(nl + 128 * g      ) * 16 + c4];
        float4 u1 = src4[(nl + 128 * g +  16) * 16 + c4];
        float4 u2 = src4[(nl + 128 * g +  32) * 16 + c4];
        float4 u3 = src4[(nl + 128 * g +  48) * 16 + c4];
        float4 u4 = src4[(nl + 128 * g +  64) * 16 + c4];
        float4 u5 = src4[(nl + 128 * g +  80) * 16 + c4];
        float4 u6 = src4[(nl + 128 * g +  96) * 16 + c4];
        float4 u7 = src4[(nl + 128 * g + 112) * 16 + c4];
        a.x += ((u0.x + u1.x) + (u2.x + u3.x)) + ((u4.x + u5.x) + (u6.x + u7.x));
        a.y += ((u0.y + u1.y) + (u2.y + u3.y)) + ((u4.y + u5.y) + (u6.y + u7.y));
        a.z += ((u0.z + u1.z) + (u2.z + u3.z)) + ((u4.z + u5.z) + (u6.z + u7.z));
        a.w += ((u0.w + u1.w) + (u2.w + u3.w)) + ((u4.w + u5.w) + (u6.w + u7.w));
    }

    float4* s4      = (float4*)smem;      // [0,1024) floats (aliases s_x; synced)
    float*  s_wpart = smem + 1024;        // 64
    float*  s_v     = smem + 1088;        // 512

    s4[t] = a;
    __syncthreads();
    if (t < 128) { float4 o = s4[t + 128]; s4[t].x += o.x; s4[t].y += o.y; s4[t].z += o.z; s4[t].w += o.w; }
    __syncthreads();
    if (t < 64)  { float4 o = s4[t + 64];  s4[t].x += o.x; s4[t].y += o.y; s4[t].z += o.z; s4[t].w += o.w; }
    __syncthreads();
    if (t < 16) {
        float4 r = s4[t];
        float4 o1 = s4[t + 16], o2 = s4[t + 32], o3 = s4[t + 48];
        s_wpart[4 * t + 0] = r.x + o1.x + o2.x + o3.x;
        s_wpart[4 * t + 1] = r.y + o1.y + o2.y + o3.y;
        s_wpart[4 * t + 2] = r.z + o1.z + o2.z + o3.z;
        s_wpart[4 * t + 3] = r.w + o1.w + o2.w + o3.w;
    }
    __syncthreads();

    // ---------- v[j] = sum_c W_out[j,c] * wpart[c]   (overlaps stage-1 wait) ----------
    {
        const int jg = t & 7;             // 8 threads per j, each 8 c's
        const float4 wa = *(const float4*)(s_wpart + jg * 8);
        const float4 wb = *(const float4*)(s_wpart + jg * 8 + 4);
        #pragma unroll
        for (int pp = 0; pp < 16; ++pp) {
            const int j = pp * 32 + (t >> 3);
            const float4* row = (const float4*)(W_out + j * CC + jg * 8);
            const float4 r0 = row[0], r1 = row[1];
            float acc = r0.x * wa.x + r0.y * wa.y + r0.z * wa.z + r0.w * wa.w
                      + r1.x * wb.x + r1.y * wb.y + r1.z * wb.z + r1.w * wb.w;
            acc += __shfl_down_sync(0xffffffffu, acc, 4);
            acc += __shfl_down_sync(0xffffffffu, acc, 2);
            acc += __shfl_down_sync(0xffffffffu, acc, 1);
            if (jg == 0) s_v[j] = acc;
        }
    }
    __syncthreads();

    // ---------- wait for all 256 stage-1 publishes ----------
    if (t == 0) spin_until(&g_d1, (s_epoch + 1u) * NBLK);
    __syncthreads();
    __threadfence();

    // ---------- out[b2, cp] = bf[cp] + sum_j hcat[b2,j] * v[j] ----------
    {
        const int b2 = t >> 3;            // 0..31
        const int jg = t & 7;             // 16 float4 (64 j's) each
        const float4* hc = (const float4*)(g_hcat + b2 * (KK * HH)) + jg * 16;
        const float4* vv = (const float4*)(s_v + jg * 64);
        float acc = 0.f;
        #pragma unroll
        for (int i = 0; i < 16; ++i) {
            const float4 h4 = hc[i];
            const float4 w4 = vv[i];
            acc += h4.x * w4.x + h4.y * w4.y + h4.z * w4.z + h4.w * w4.w;
        }
        acc += __shfl_down_sync(0xffffffffu, acc, 4);
        acc += __shfl_down_sync(0xffffffffu, acc, 2);
        acc += __shfl_down_sync(0xffffffffu, acc, 1);
        if (jg == 0) out[b2 * CC + cp] = bf[cp] + acc;   // direct store — no atomics
    }
}

extern "C" void kernel_launch(void* const* d_in, const int* in_sizes, int n_in,
                              void* d_out, int out_size)
{
    const float* x       = (const float*)d_in[0];
    const float* W_heads = (const float*)d_in[1];
    // d_in[2], d_in[3]: a1_heads/a2_heads — drop out (uniform softmax)
    const float* W_out   = (const float*)d_in[4];
    // d_in[5], d_in[6]: a1_out/a2_out — drop out
    const float* Wf      = (const float*)d_in[7];
    const float* bf      = (const float*)d_in[8];
    float* out           = (float*)d_out;

    gat_fused<<<NBLK, TPB>>>(x, W_heads, W_out, Wf, bf, out);
}

// round 14
// speedup vs baseline: 1.8045x; 1.8045x over previous
#include <cuda_runtime.h>

// B=32, S=12, F=128, K=8, H=64, C=64, N=512
#define BB    32
#define SEQ   12
#define FF    128
#define KK    8
#define HH    64
#define CC    64
#define NNN   512
#define NBLK  256                    // dual-role blocks: (b,k) stage1 + (cp,p) Wf chunk
#define TPB   256

// Scratch + sync (allocation-free rule: __device__ globals).
// All data buffers fully overwritten every epoch; counters monotonic across replays.
__device__ float g_part[KK * BB * CC];        // [k][b*64+c] per-k WhO partials
__device__ float g_wpart[4 * CC * CC];        // [p][cp*64+c] per-chunk Wf sums
__device__ unsigned int g_tick = 0;
__device__ unsigned int g_d1 = 0;

__device__ __forceinline__ void spin_until(volatile unsigned int* p, unsigned int target)
{
    while (*p < target) { __nanosleep(32); }
}

__global__ void __launch_bounds__(TPB, 2) gat_fused(
    const float* __restrict__ x,        // (32,12,128)
    const float* __restrict__ W_heads,  // (8,128,64)
    const float* __restrict__ W_out,    // (512,64)
    const float* __restrict__ Wf,       // (64, 512*64)
    const float* __restrict__ bf,       // (64,)
    float* __restrict__ out)            // (32,64)
{
    // Disjoint smem regions (6.2 KB) — no aliasing, minimal syncs.
    __shared__ float s_x[FF];           // 128
    __shared__ float s_hcat[HH];        // 64  (this block's k-slice of hcat)
    __shared__ float s_p[TPB];          // 256 reduction scratch
    __shared__ float4 s4[TPB];          // 1024 floats Wf reduction
    __shared__ float s_wpart[CC];       // 64
    __shared__ unsigned int s_epoch;

    const int blk = blockIdx.x;
    const int t   = threadIdx.x;

    if (t == 0) s_epoch = atomicAdd(&g_tick, 1u) / NBLK;

    const int b  = blk >> 3, k = blk & 7;      // stage-1 task
    const int cp = blk >> 2, p = blk & 3;      // Wf task (32 KB chunk)

    if (t < FF) s_x[t] = x[b * SEQ * FF + (SEQ - 1) * FF + t];

    // ---- front-issue the 8 Wf LDG.128 (R8-measured-best distribution) ----
    const float4* src4 = (const float4*)(Wf + (size_t)cp * (NNN * CC) + p * (128 * CC));
    const int c4 = t & 15;
    const int nl = t >> 4;
    float4 v0 = src4[(nl      ) * 16 + c4];
    float4 v1 = src4[(nl +  16) * 16 + c4];
    float4 v2 = src4[(nl +  32) * 16 + c4];
    float4 v3 = src4[(nl +  48) * 16 + c4];
    float4 v4 = src4[(nl +  64) * 16 + c4];
    float4 v5 = src4[(nl +  80) * 16 + c4];
    float4 v6 = src4[(nl +  96) * 16 + c4];
    float4 v7 = src4[(nl + 112) * 16 + c4];

    __syncthreads();                    // s_x ready

    // ---- stage-1 (R8 exact pattern): 4 threads per h ----
    {
        const int h  = t >> 2;
        const int fg = t & 3;
        const float* wp = W_heads + (size_t)k * FF * HH + h;
        float acc = 0.f;
        #pragma unroll
        for (int i = 0; i < 32; ++i) {
            const int f = fg * 32 + i;
            acc = fmaf(s_x[f], wp[f * HH], acc);
        }
        acc += __shfl_down_sync(0xffffffffu, acc, 2);
        acc += __shfl_down_sync(0xffffffffu, acc, 1);
        if (fg == 0) s_hcat[h] = acc > 0.f ? acc : expm1f(acc);   // local only
    }
    __syncthreads();

    // ---- per-k WhO partial: part[c] = sum_h s_hcat[h] * W_out[k*64+h, c] ----
    {
        const int c  = t & 63;
        const int hg = t >> 6;          // 4 groups of 16 h
        const float* wo = W_out + (size_t)(k * HH + hg * 16) * CC + c;
        float acc = 0.f;
        #pragma unroll
        for (int i = 0; i < 16; ++i)
            acc = fmaf(s_hcat[hg * 16 + i], wo[i * CC], acc);
        s_p[t] = acc;
    }
    __syncthreads();
    if (t < CC)
        g_part[k * (BB * CC) + b * CC + t] =
            s_p[t] + s_p[t + 64] + s_p[t + 128] + s_p[t + 192];

    // ---- Wf chunk reduce (loads long since arrived) ----
    float4 a;
    a.x = ((v0.x + v1.x) + (v2.x + v3.x)) + ((v4.x + v5.x) + (v6.x + v7.x));
    a.y = ((v0.y + v1.y) + (v2.y + v3.y)) + ((v4.y + v5.y) + (v6.y + v7.y));
    a.z = ((v0.z + v1.z) + (v2.z + v3.z)) + ((v4.z + v5.z) + (v6.z + v7.z));
    a.w = ((v0.w + v1.w) + (v2.w + v3.w)) + ((v4.w + v5.w) + (v6.w + v7.w));
    s4[t] = a;
    __syncthreads();
    if (t < 128) { float4 o = s4[t + 128]; s4[t].x += o.x; s4[t].y += o.y; s4[t].z += o.z; s4[t].w += o.w; }
    __syncthreads();
    if (t < 64)  { float4 o = s4[t + 64];  s4[t].x += o.x; s4[t].y += o.y; s4[t].z += o.z; s4[t].w += o.w; }
    __syncthreads();
    if (t < 16) {
        float4 r = s4[t];
        float4 o1 = s4[t + 16], o2 = s4[t + 32], o3 = s4[t + 48];
        g_wpart[p * (CC * CC) + cp * CC + 4 * t + 0] = r.x + o1.x + o2.x + o3.x;
        g_wpart[p * (CC * CC) + cp * CC + 4 * t + 1] = r.y + o1.y + o2.y + o3.y;
        g_wpart[p * (CC * CC) + cp * CC + 4 * t + 2] = r.z + o1.z + o2.z + o3.z;
        g_wpart[p * (CC * CC) + cp * CC + 4 * t + 3] = r.w + o1.w + o2.w + o3.w;
    }

    // ---- single publish (both g_part and g_wpart written) ----
    __threadfence();
    __syncthreads();
    if (t == 0) atomicAdd(&g_d1, 1u);

    if (p != 0) return;                 // only 64 epilogue blocks remain

    // ---- the ONE barrier: wait for all 256 publishes ----
    if (t == 0) spin_until(&g_d1, (s_epoch + 1u) * NBLK);
    __syncthreads();
    __threadfence();

    // ---- assemble full wpart for this cp ----
    if (t < CC) {
        s_wpart[t] = g_wpart[0 * (CC * CC) + cp * CC + t]
                   + g_wpart[1 * (CC * CC) + cp * CC + t]
                   + g_wpart[2 * (CC * CC) + cp * CC + t]
                   + g_wpart[3 * (CC * CC) + cp * CC + t];
    }
    __syncthreads();

    // ---- out[b2,cp] = bf[cp] + sum_k sum_c part[k][b2,c] * wpart[c] ----
    {
        const int b2 = t >> 3;          // 0..31
        const int jg = t & 7;           // 8 c's each
        const float4 wa = *(const float4*)(s_wpart + jg * 8);
        const float4 wb = *(const float4*)(s_wpart + jg * 8 + 4);
        float acc = 0.f;
        #pragma unroll
        for (int kk2 = 0; kk2 < KK; ++kk2) {
            const float4* pr = (const float4*)(g_part + kk2 * (BB * CC) + b2 * CC + jg * 8);
            const float4 r0 = pr[0], r1 = pr[1];
            acc += r0.x * wa.x + r0.y * wa.y + r0.z * wa.z + r0.w * wa.w
                 + r1.x * wb.x + r1.y * wb.y + r1.z * wb.z + r1.w * wb.w;
        }
        acc += __shfl_down_sync(0xffffffffu, acc, 4);
        acc += __shfl_down_sync(0xffffffffu, acc, 2);
        acc += __shfl_down_sync(0xffffffffu, acc, 1);
        if (jg == 0) out[b2 * CC + cp] = bf[cp] + acc;   // direct store — no atomics
    }
}

extern "C" void kernel_launch(void* const* d_in, const int* in_sizes, int n_in,
                              void* d_out, int out_size)
{
    const float* x       = (const float*)d_in[0];
    const float* W_heads = (const float*)d_in[1];
    // d_in[2], d_in[3]: a1_heads/a2_heads — drop out (uniform softmax)
    const float* W_out   = (const float*)d_in[4];
    // d_in[5], d_in[6]: a1_out/a2_out — drop out
    const float* Wf      = (const float*)d_in[7];
    const float* bf      = (const float*)d_in[8];
    float* out           = (float*)d_out;

    gat_fused<<<NBLK, TPB>>>(x, W_heads, W_out, Wf, bf, out);
}

// round 15
// speedup vs baseline: 1.8462x; 1.0231x over previous
#include <cuda_runtime.h>

// B=32, S=12, F=128, K=8, H=64, C=64, N=512
#define BB    32
#define SEQ   12
#define FF    128
#define KK    8
#define HH    64
#define CC    64
#define NNN   512
#define NBLK  256                    // dual-role blocks: (b,k) stage1 + (cp,p) Wf chunk
#define NEPI  64                     // epilogue blocks (p==0)
#define TPB   256

// Scratch + sync (allocation-free rule: __device__ globals).
// Counters monotonic across graph replays; padded to distinct 128B lines.
__device__ float g_part[KK * BB * CC];        // [k][b*64+c] per-k WhO partials
__device__ float g_wpart[4 * CC * CC];        // [p][cp*64+c] per-chunk Wf sums
__device__ __align__(128) unsigned int g_d1[32];    // publish count (element 0)
__device__ __align__(128) unsigned int g_tick[32];  // epilogue tickets (element 0)

__device__ __forceinline__ void spin_until(volatile unsigned int* p, unsigned int target)
{
    while (*p < target) { __nanosleep(32); }
}

__global__ void __launch_bounds__(TPB, 2) gat_fused(
    const float* __restrict__ x,        // (32,12,128)
    const float* __restrict__ W_heads,  // (8,128,64)
    const float* __restrict__ W_out,    // (512,64)
    const float* __restrict__ Wf,       // (64, 512*64)
    const float* __restrict__ bf,       // (64,)
    float* __restrict__ out)            // (32,64)
{
    // Disjoint smem regions — no aliasing.
    __shared__ float s_x[FF];           // 128
    __shared__ float s_hcat[HH];        // 64
    __shared__ float s_p[TPB];          // 256
    __shared__ float4 s4[TPB];          // 1024 floats
    __shared__ float s_wpart[CC];       // 64

    const int blk = blockIdx.x;
    const int t   = threadIdx.x;

    const int b  = blk >> 3, k = blk & 7;      // stage-1 task
    const int cp = blk >> 2, p = blk & 3;      // Wf task (32 KB chunk)

    if (t < FF) s_x[t] = x[b * SEQ * FF + (SEQ - 1) * FF + t];

    // ---- front-issue the 8 Wf LDG.128 (DRAM long pole) ----
    const float4* src4 = (const float4*)(Wf + (size_t)cp * (NNN * CC) + p * (128 * CC));
    const int c4 = t & 15;
    const int nl = t >> 4;
    float4 v0 = src4[(nl      ) * 16 + c4];
    float4 v1 = src4[(nl +  16) * 16 + c4];
    float4 v2 = src4[(nl +  32) * 16 + c4];
    float4 v3 = src4[(nl +  48) * 16 + c4];
    float4 v4 = src4[(nl +  64) * 16 + c4];
    float4 v5 = src4[(nl +  80) * 16 + c4];
    float4 v6 = src4[(nl +  96) * 16 + c4];
    float4 v7 = src4[(nl + 112) * 16 + c4];

    // ---- pre-issue W_out slice (L2-shared by 32 blocks) into registers ----
    const int c  = t & 63;
    const int hg = t >> 6;              // 4 groups of 16 h
    float wo[16];
    {
        const float* wop = W_out + (size_t)(k * HH + hg * 16) * CC + c;
        #pragma unroll
        for (int i = 0; i < 16; ++i) wo[i] = wop[i * CC];
    }

    __syncthreads();                    // s_x ready (no atomic gating this sync)

    // ---- stage-1 (R8/R14 exact pattern): 4 threads per h ----
    {
        const int h  = t >> 2;
        const int fg = t & 3;
        const float* wp = W_heads + (size_t)k * FF * HH + h;
        float acc = 0.f;
        #pragma unroll
        for (int i = 0; i < 32; ++i) {
            const int f = fg * 32 + i;
            acc = fmaf(s_x[f], wp[f * HH], acc);
        }
        acc += __shfl_down_sync(0xffffffffu, acc, 2);
        acc += __shfl_down_sync(0xffffffffu, acc, 1);
        if (fg == 0) s_hcat[h] = acc > 0.f ? acc : expm1f(acc);
    }
    __syncthreads();

    // ---- per-k WhO partial from registers: part[c] = sum_h s_hcat[h]*wo[h] ----
    {
        float acc = 0.f;
        #pragma unroll
        for (int i = 0; i < 16; ++i)
            acc = fmaf(s_hcat[hg * 16 + i], wo[i], acc);
        s_p[t] = acc;
    }
    __syncthreads();
    if (t < CC)
        g_part[k * (BB * CC) + b * CC + t] =
            s_p[t] + s_p[t + 64] + s_p[t + 128] + s_p[t + 192];

    // ---- Wf chunk reduce (loads long since arrived) ----
    float4 a;
    a.x = ((v0.x + v1.x) + (v2.x + v3.x)) + ((v4.x + v5.x) + (v6.x + v7.x));
    a.y = ((v0.y + v1.y) + (v2.y + v3.y)) + ((v4.y + v5.y) + (v6.y + v7.y));
    a.z = ((v0.z + v1.z) + (v2.z + v3.z)) + ((v4.z + v5.z) + (v6.z + v7.z));
    a.w = ((v0.w + v1.w) + (v2.w + v3.w)) + ((v4.w + v5.w) + (v6.w + v7.w));
    s4[t] = a;
    __syncthreads();
    if (t < 128) { float4 o = s4[t + 128]; s4[t].x += o.x; s4[t].y += o.y; s4[t].z += o.z; s4[t].w += o.w; }
    __syncthreads();
    if (t < 64)  { float4 o = s4[t + 64];  s4[t].x += o.x; s4[t].y += o.y; s4[t].z += o.z; s4[t].w += o.w; }
    __syncthreads();
    if (t < 16) {
        float4 r = s4[t];
        float4 o1 = s4[t + 16], o2 = s4[t + 32], o3 = s4[t + 48];
        g_wpart[p * (CC * CC) + cp * CC + 4 * t + 0] = r.x + o1.x + o2.x + o3.x;
        g_wpart[p * (CC * CC) + cp * CC + 4 * t + 1] = r.y + o1.y + o2.y + o3.y;
        g_wpart[p * (CC * CC) + cp * CC + 4 * t + 2] = r.z + o1.z + o2.z + o3.z;
        g_wpart[p * (CC * CC) + cp * CC + 4 * t + 3] = r.w + o1.w + o2.w + o3.w;
    }

    // ---- single publish (return value unused -> RED) ----
    __threadfence();
    __syncthreads();
    if (t == 0) atomicAdd(&g_d1[0], 1u);

    if (p != 0) return;                 // 192 blocks exit; 64 epilogue blocks remain

    // ---- epoch ticket taken HERE (64-way, off everyone else's critical path) ----
    __shared__ unsigned int s_target;
    if (t == 0) {
        const unsigned int epoch = atomicAdd(&g_tick[0], 1u) / NEPI;
        s_target = (epoch + 1u) * NBLK;
        spin_until(&g_d1[0], s_target);
    }
    __syncthreads();
    __threadfence();

    // ---- assemble full wpart for this cp ----
    if (t < CC) {
        s_wpart[t] = g_wpart[0 * (CC * CC) + cp * CC + t]
                   + g_wpart[1 * (CC * CC) + cp * CC + t]
                   + g_wpart[2 * (CC * CC) + cp * CC + t]
                   + g_wpart[3 * (CC * CC) + cp * CC + t];
    }
    __syncthreads();

    // ---- out[b2,cp] = bf[cp] + sum_k sum_c part[k][b2,c] * wpart[c] ----
    {
        const int b2 = t >> 3;          // 0..31
        const int jg = t & 7;           // 8 c's each
        const float4 wa = *(const float4*)(s_wpart + jg * 8);
        const float4 wb = *(const float4*)(s_wpart + jg * 8 + 4);
        float acc = 0.f;
        #pragma unroll
        for (int kk2 = 0; kk2 < KK; ++kk2) {
            const float4* pr = (const float4*)(g_part + kk2 * (BB * CC) + b2 * CC + jg * 8);
            const float4 r0 = pr[0], r1 = pr[1];
            acc += r0.x * wa.x + r0.y * wa.y + r0.z * wa.z + r0.w * wa.w
                 + r1.x * wb.x + r1.y * wb.y + r1.z * wb.z + r1.w * wb.w;
        }
        acc += __shfl_down_sync(0xffffffffu, acc, 4);
        acc += __shfl_down_sync(0xffffffffu, acc, 2);
        acc += __shfl_down_sync(0xffffffffu, acc, 1);
        if (jg == 0) out[b2 * CC + cp] = bf[cp] + acc;   // direct store — no atomics
    }
}

extern "C" void kernel_launch(void* const* d_in, const int* in_sizes, int n_in,
                              void* d_out, int out_size)
{
    const float* x       = (const float*)d_in[0];
    const float* W_heads = (const float*)d_in[1];
    // d_in[2], d_in[3]: a1_heads/a2_heads — drop out (uniform softmax)
    const float* W_out   = (const float*)d_in[4];
    // d_in[5], d_in[6]: a1_out/a2_out — drop out
    const float* Wf      = (const float*)d_in[7];
    const float* bf      = (const float*)d_in[8];
    float* out           = (float*)d_out;

    gat_fused<<<NBLK, TPB>>>(x, W_heads, W_out, Wf, bf, out);
}